// round 3
// baseline (speedup 1.0000x reference)
#include <cuda_runtime.h>
#include <math.h>
#include <stdint.h>

// ----------------------------------------------------------------------------
// NonLinearTSQ: gated tensor-square, tensor-core (tf32 mma.sync) version.
//   in : 64x0e + 32x1o   (160 floats/node)
//   out: 64x0e + 32x1o + 16x2e (240 floats/node), B = 32768
//
//   out0 = packed-symmetric quadratic features (K=2608->2624) x Wc[2624,64]
//   out1 = (s @ Wsv1) contracted with v, per 4-wide q chunks
//   out2 = (v_j @ Wvv2) -> tv, contracted with v_i, CG epilogue
// ----------------------------------------------------------------------------

#define KSS   2080
#define KREAL 2608
#define KPAD  2624          // 41 chunks of 64

__device__ __align__(16) float g_Wc[KPAD * 64];   // tf32-rounded packed weights
__device__ int g_puv[KPAD];                        // (type<<16)|(u<<8)|v

// ---------------------------------------------------------------- helpers
__device__ __forceinline__ uint32_t cvt_tf32(float x) {
    uint32_t u;
    asm("cvt.rna.tf32.f32 %0, %1;" : "=r"(u) : "f"(x));
    return u;
}

__device__ __forceinline__ void mma_tf32(float c[4],
                                         uint32_t a0, uint32_t a1,
                                         uint32_t a2, uint32_t a3,
                                         uint32_t b0, uint32_t b1) {
    asm volatile(
        "mma.sync.aligned.m16n8k8.row.col.f32.tf32.tf32.f32 "
        "{%0,%1,%2,%3}, {%4,%5,%6,%7}, {%8,%9}, {%0,%1,%2,%3};"
        : "+f"(c[0]), "+f"(c[1]), "+f"(c[2]), "+f"(c[3])
        : "r"(a0), "r"(a1), "r"(a2), "r"(a3), "r"(b0), "r"(b1));
}

// ---------------------------------------------------------------- prep kernel
__global__ void prep(const float* __restrict__ Wss0,
                     const float* __restrict__ Wvv0)
{
    __shared__ int sh_u, sh_v, sh_t;
    int k = blockIdx.x;
    if (threadIdx.x == 0) {
        int u = 0, v = 0, t = 2;
        if (k < KSS) {
            int rem = k, row = 64;
            while (rem >= row) { rem -= row; row--; }
            u = 64 - row; v = u + rem; t = 0;
        } else if (k < KREAL) {
            int rem = k - KSS, row = 32;
            while (rem >= row) { rem -= row; row--; }
            u = 32 - row; v = u + rem; t = 1;
        }
        sh_u = u; sh_v = v; sh_t = t;
        g_puv[k] = (t << 16) | (u << 8) | v;
    }
    __syncthreads();
    int p = threadIdx.x;
    int u = sh_u, v = sh_v, t = sh_t;
    const float C0 = 1.0f / sqrtf(5120.0f);
    const float RS3 = 0.5773502691896258f;
    float val = 0.0f;
    if (t == 0) {
        val = Wss0[(u * 64 + v) * 64 + p];
        if (u != v) val += Wss0[(v * 64 + u) * 64 + p];
        val *= C0;
    } else if (t == 1) {
        val = Wvv0[(u * 32 + v) * 64 + p];
        if (u != v) val += Wvv0[(v * 32 + u) * 64 + p];
        val *= C0 * RS3;
    }
    g_Wc[k * 64 + p] = __uint_as_float(cvt_tf32(val));
}

// ------------------------------------------------------------------ main kernel
// 64 nodes per block, 256 threads (8 warps).
// smem: sv[160][64] | U[12672] | gv[32]
#define U_FLOATS   12672
#define SMEM_FLOATS (160 * 64 + U_FLOATS + 32)

__global__ __launch_bounds__(256, 2)
void k_main(const float* __restrict__ x, const float* __restrict__ gates,
            const float* __restrict__ Wsv1, const float* __restrict__ Wvv2,
            float* __restrict__ out, int B)
{
    extern __shared__ float sm[];
    float* sv = sm;                  // [160][64]
    float* U  = sm + 160 * 64;       // scratch, 12672 floats
    float* gv = U + U_FLOATS;        // 32

    const int tid  = threadIdx.x;
    const int lane = tid & 31;
    const int warp = tid >> 5;
    const int gid  = lane >> 2;      // 0..7
    const int tig  = lane & 3;       // 0..3
    const int node0 = blockIdx.x * 64;

    // warp tile origins
    const int m0   = (warp & 3) * 16;    // node tile
    const int n0p2 = (warp >> 2) * 32;   // phase-2 output tile (N=64)
    const int n0w  = (warp >> 2) * 64;   // phase-3/4 output tile (N=128)

    if (tid < 32) gv[tid] = tanhf(gates[tid]);
    __syncthreads();

    // ---- Phase 1: load tile, nonlinearity, transpose to feature-major
    for (int idx = tid; idx < 2560; idx += 256) {
        int node = idx / 40;
        int fq = idx - node * 40;
        float4 xv = make_float4(0.f, 0.f, 0.f, 0.f);
        if (node0 + node < B)
            xv = *(const float4*)(x + (size_t)(node0 + node) * 160 + fq * 4);
        float vals[4] = {xv.x, xv.y, xv.z, xv.w};
        #pragma unroll
        for (int jj = 0; jj < 4; jj++) {
            int f = fq * 4 + jj;
            float val = vals[jj];
            if (f < 64) val = tanhf(val);
            else        val *= gv[(f - 64) / 3];
            sv[f * 64 + node] = val;
        }
    }
    __syncthreads();

    // =======================================================================
    // Phase 2: out0 = z[2624] x Wc[2624,64], tensor GEMM M=64,N=64
    // zbuf pitch 72, wbuf pitch 72 (tig*8+gid distinct mod 32 -> conflict-free)
    // =======================================================================
    float* zbuf = U;             // [64][72]
    float* wbuf = U + 64 * 72;   // [64][72]

    float c2a[4][4];
    #pragma unroll
    for (int j = 0; j < 4; j++)
        #pragma unroll
        for (int i = 0; i < 4; i++) c2a[j][i] = 0.f;

    for (int ck = 0; ck < 41; ck++) {
        int kbase = ck * 64;
        // build z chunk (tf32-rounded)
        #pragma unroll
        for (int t = 0; t < 16; t++) {
            int idx = tid + t * 256;
            int kk = idx >> 6;
            int node = idx & 63;
            int k = kbase + kk;
            int puv = g_puv[k];
            int typ = puv >> 16;
            int u = (puv >> 8) & 255, vch = puv & 255;
            float z = 0.f;
            if (typ == 0) {
                z = sv[u * 64 + node] * sv[vch * 64 + node];
            } else if (typ == 1) {
                const float* pa = sv + (64 + 3 * u) * 64 + node;
                const float* pb = sv + (64 + 3 * vch) * 64 + node;
                z = pa[0] * pb[0] + pa[64] * pb[64] + pa[128] * pb[128];
            }
            zbuf[kk * 72 + node] = __uint_as_float(cvt_tf32(z));
        }
        // stage Wc chunk (already tf32)
        #pragma unroll
        for (int t = 0; t < 4; t++) {
            int idx = tid + t * 256;
            int kk = idx >> 4;
            int p = (idx & 15) * 4;
            float4 w = *(const float4*)(g_Wc + (size_t)(kbase + kk) * 64 + p);
            *(float4*)(wbuf + kk * 72 + p) = w;
        }
        __syncthreads();
        // 8 k-steps of m16n8k8
        #pragma unroll
        for (int ks = 0; ks < 8; ks++) {
            int kb = ks * 8;
            uint32_t a0 = __float_as_uint(zbuf[(kb + tig) * 72 + m0 + gid]);
            uint32_t a1 = __float_as_uint(zbuf[(kb + tig) * 72 + m0 + gid + 8]);
            uint32_t a2 = __float_as_uint(zbuf[(kb + tig + 4) * 72 + m0 + gid]);
            uint32_t a3 = __float_as_uint(zbuf[(kb + tig + 4) * 72 + m0 + gid + 8]);
            #pragma unroll
            for (int j = 0; j < 4; j++) {
                uint32_t b0 = __float_as_uint(wbuf[(kb + tig) * 72 + n0p2 + j * 8 + gid]);
                uint32_t b1 = __float_as_uint(wbuf[(kb + tig + 4) * 72 + n0p2 + j * 8 + gid]);
                mma_tf32(c2a[j], a0, a1, a2, a3, b0, b1);
            }
        }
        __syncthreads();
    }
    // write out0
    {
        int nodeA = node0 + m0 + gid;
        int nodeB = nodeA + 8;
        #pragma unroll
        for (int j = 0; j < 4; j++) {
            int p = n0p2 + j * 8 + 2 * tig;
            if (nodeA < B)
                *(float2*)(out + (size_t)nodeA * 240 + p) = make_float2(c2a[j][0], c2a[j][1]);
            if (nodeB < B)
                *(float2*)(out + (size_t)nodeB * 240 + p) = make_float2(c2a[j][2], c2a[j][3]);
        }
    }

    // =======================================================================
    // Phase 3: out1. 8 chunks of 4 q's. GEMM M=64, N=128 (=32v x 4q), K=64.
    // B pitch 136; A' pitch 65.
    // =======================================================================
    const float C1 = 0.022097086912079612f;   // 1/sqrt(2048)
    for (int qc = 0; qc < 8; qc++) {
        // stage B: U[u*136 + v*4+ql]
        #pragma unroll
        for (int t = 0; t < 32; t++) {
            int idx = tid + t * 256;
            int u = idx >> 7;
            int col = idx & 127;
            int v = col >> 2, ql = col & 3;
            U[u * 136 + col] =
                __uint_as_float(cvt_tf32(Wsv1[u * 1024 + v * 32 + qc * 4 + ql]));
        }
        __syncthreads();
        float c[8][4];
        #pragma unroll
        for (int j = 0; j < 8; j++)
            #pragma unroll
            for (int i = 0; i < 4; i++) c[j][i] = 0.f;
        #pragma unroll
        for (int ks = 0; ks < 8; ks++) {
            int kb = ks * 8;
            uint32_t a0 = cvt_tf32(sv[(kb + tig) * 64 + m0 + gid]);
            uint32_t a1 = cvt_tf32(sv[(kb + tig) * 64 + m0 + gid + 8]);
            uint32_t a2 = cvt_tf32(sv[(kb + tig + 4) * 64 + m0 + gid]);
            uint32_t a3 = cvt_tf32(sv[(kb + tig + 4) * 64 + m0 + gid + 8]);
            #pragma unroll
            for (int j = 0; j < 8; j++) {
                int col = n0w + j * 8 + gid;
                uint32_t b0 = __float_as_uint(U[(kb + tig) * 136 + col]);
                uint32_t b1 = __float_as_uint(U[(kb + tig + 4) * 136 + col]);
                mma_tf32(c[j], a0, a1, a2, a3, b0, b1);
            }
        }
        __syncthreads();
        // write A' (reuse U), pitch 65
        #pragma unroll
        for (int j = 0; j < 8; j++) {
            int col = n0w + j * 8 + 2 * tig;
            U[col * 65 + m0 + gid]           = c[j][0];
            U[(col + 1) * 65 + m0 + gid]     = c[j][1];
            U[col * 65 + m0 + gid + 8]       = c[j][2];
            U[(col + 1) * 65 + m0 + gid + 8] = c[j][3];
        }
        __syncthreads();
        // epilogue: 256 items (node, ql)
        {
            int node = tid & 63;
            int ql = tid >> 6;
            float o0 = 0.f, o1 = 0.f, o2 = 0.f;
            #pragma unroll 8
            for (int v = 0; v < 32; v++) {
                float a = U[(v * 4 + ql) * 65 + node];
                const float* pvv = sv + (64 + 3 * v) * 64 + node;
                o0 += a * pvv[0];
                o1 += a * pvv[64];
                o2 += a * pvv[128];
            }
            int node_g = node0 + node;
            if (node_g < B) {
                float* o = out + (size_t)node_g * 240 + 64 + (qc * 4 + ql) * 3;
                o[0] = C1 * o0; o[1] = C1 * o1; o[2] = C1 * o2;
            }
        }
        __syncthreads();
    }

    // =======================================================================
    // Phase 4: out2. 4 u-chunks x 3 components. GEMM M=64, N=128, K=32.
    // B4 pitch 136 (4352 floats), tvb pitch 65 at U+4352 (8320 floats).
    // =======================================================================
    float S[4][9];
    #pragma unroll
    for (int t = 0; t < 4; t++)
        #pragma unroll
        for (int i = 0; i < 9; i++) S[t][i] = 0.f;

    float* B4  = U;
    float* tvb = U + 32 * 136;

    for (int uc = 0; uc < 4; uc++) {
        // stage B4[v*136 + ul*16 + r]
        #pragma unroll
        for (int t = 0; t < 16; t++) {
            int idx = tid + t * 256;
            int v = idx >> 7;
            int col = idx & 127;
            int ul = col >> 4, rr = col & 15;
            B4[v * 136 + col] =
                __uint_as_float(cvt_tf32(Wvv2[((uc * 8 + ul) * 32 + v) * 16 + rr]));
        }
        __syncthreads();
        #pragma unroll
        for (int j = 0; j < 3; j++) {
            float c[8][4];
            #pragma unroll
            for (int jj = 0; jj < 8; jj++)
                #pragma unroll
                for (int i = 0; i < 4; i++) c[jj][i] = 0.f;
            #pragma unroll
            for (int ks = 0; ks < 4; ks++) {
                int kb = ks * 8;
                uint32_t a0 = cvt_tf32(sv[(64 + 3 * (kb + tig) + j) * 64 + m0 + gid]);
                uint32_t a1 = cvt_tf32(sv[(64 + 3 * (kb + tig) + j) * 64 + m0 + gid + 8]);
                uint32_t a2 = cvt_tf32(sv[(64 + 3 * (kb + tig + 4) + j) * 64 + m0 + gid]);
                uint32_t a3 = cvt_tf32(sv[(64 + 3 * (kb + tig + 4) + j) * 64 + m0 + gid + 8]);
                #pragma unroll
                for (int jn = 0; jn < 8; jn++) {
                    int col = n0w + jn * 8 + gid;
                    uint32_t b0 = __float_as_uint(B4[(kb + tig) * 136 + col]);
                    uint32_t b1 = __float_as_uint(B4[(kb + tig + 4) * 136 + col]);
                    mma_tf32(c[jn], a0, a1, a2, a3, b0, b1);
                }
            }
            __syncthreads();   // prior S-accum reads of tvb done before overwrite
            #pragma unroll
            for (int jn = 0; jn < 8; jn++) {
                int col = n0w + jn * 8 + 2 * tig;
                tvb[col * 65 + m0 + gid]           = c[jn][0];
                tvb[(col + 1) * 65 + m0 + gid]     = c[jn][1];
                tvb[col * 65 + m0 + gid + 8]       = c[jn][2];
                tvb[(col + 1) * 65 + m0 + gid + 8] = c[jn][3];
            }
            __syncthreads();
            // S accumulation: 1024 items (node, r)
            #pragma unroll
            for (int t = 0; t < 4; t++) {
                int it = tid + t * 256;
                int node = it & 63;
                int r = it >> 6;
                #pragma unroll
                for (int ul = 0; ul < 8; ul++) {
                    float tvv = tvb[(ul * 16 + r) * 65 + node];
                    const float* pu_ = sv + (64 + 3 * (uc * 8 + ul)) * 64 + node;
                    S[t][0 * 3 + j] += pu_[0]   * tvv;
                    S[t][1 * 3 + j] += pu_[64]  * tvv;
                    S[t][2 * 3 + j] += pu_[128] * tvv;
                }
            }
            __syncthreads();
        }
    }
    // finalize out2 via CG contraction
    const float C2R2 = (1.f / 32.f) * 0.7071067811865475f;
    const float C2R6 = (1.f / 32.f) * 0.4082482904638630f;
    #pragma unroll
    for (int t = 0; t < 4; t++) {
        int it = tid + t * 256;
        int node = node0 + (it & 63);
        int r = it >> 6;
        if (node < B) {
            float* o = out + (size_t)node * 240 + 160 + r * 5;
            o[0] = C2R2 * (S[t][0 * 3 + 1] + S[t][1 * 3 + 0]);
            o[1] = C2R2 * (S[t][1 * 3 + 2] + S[t][2 * 3 + 1]);
            o[2] = C2R6 * (2.f * S[t][2 * 3 + 2] - S[t][0 * 3 + 0] - S[t][1 * 3 + 1]);
            o[3] = C2R2 * (S[t][0 * 3 + 2] + S[t][2 * 3 + 0]);
            o[4] = C2R2 * (S[t][0 * 3 + 0] - S[t][1 * 3 + 1]);
        }
    }
}

// ------------------------------------------------------------------- launcher
extern "C" void kernel_launch(void* const* d_in, const int* in_sizes, int n_in,
                              void* d_out, int out_size)
{
    const float* x     = (const float*)d_in[0];
    const float* gates = (const float*)d_in[1];
    const float* Wss0  = (const float*)d_in[2];
    const float* Wsv1  = (const float*)d_in[3];
    const float* Wvv0  = (const float*)d_in[4];
    const float* Wvv2  = (const float*)d_in[5];
    float* out = (float*)d_out;

    int B = in_sizes[0] / 160;

    prep<<<KPAD, 64>>>(Wss0, Wvv0);

    size_t smem_bytes = (size_t)SMEM_FLOATS * sizeof(float);  // 91,776 B
    cudaFuncSetAttribute(k_main, cudaFuncAttributeMaxDynamicSharedMemorySize,
                         (int)smem_bytes);
    int grid = (B + 63) / 64;
    k_main<<<grid, 256, smem_bytes>>>(x, gates, Wsv1, Wvv2, out, B);
}

// round 5
// speedup vs baseline: 1.2439x; 1.2439x over previous
#include <cuda_runtime.h>
#include <cuda_fp16.h>
#include <math.h>
#include <stdint.h>

// ----------------------------------------------------------------------------
// NonLinearTSQ: gated tensor-square, fp16 mma.sync (m16n8k16, fp32 accum).
//   in : 64x0e + 32x1o   (160 floats/node)
//   out: 64x0e + 32x1o + 16x2e (240 floats/node), B = 32768
// ----------------------------------------------------------------------------

#define KSS   2080
#define KREAL 2608
#define KPAD  2624
#define K2PAD 1312          // KPAD/2, 41 chunks of 32 half2-rows

__device__ __align__(16) half2 g_Wch2[K2PAD * 64];   // out0 weights, k-paired
__device__ __align__(16) half2 g_Wsv1p[32768];       // [qc][u2][v*4+ql]
__device__ __align__(16) half2 g_Wvv2p[8192];        // [uc][v2][ul*16+r]
__device__ int g_puv[KPAD];                          // (type<<16)|(u<<8)|v

// ---------------------------------------------------------------- helpers
__device__ __forceinline__ void decode_k(int k, int& u, int& v, int& t) {
    u = 0; v = 0; t = 2;
    if (k < KSS) {
        int rem = k, row = 64;
        while (rem >= row) { rem -= row; row--; }
        u = 64 - row; v = u + rem; t = 0;
    } else if (k < KREAL) {
        int rem = k - KSS, row = 32;
        while (rem >= row) { rem -= row; row--; }
        u = 32 - row; v = u + rem; t = 1;
    }
}

__device__ __forceinline__ void mma_f16(float* c,
                                        uint32_t a0, uint32_t a1,
                                        uint32_t a2, uint32_t a3,
                                        uint32_t b0, uint32_t b1) {
    asm volatile(
        "mma.sync.aligned.m16n8k16.row.col.f32.f16.f16.f32 "
        "{%0,%1,%2,%3}, {%4,%5,%6,%7}, {%8,%9}, {%0,%1,%2,%3};"
        : "+f"(c[0]), "+f"(c[1]), "+f"(c[2]), "+f"(c[3])
        : "r"(a0), "r"(a1), "r"(a2), "r"(a3), "r"(b0), "r"(b1));
}

// ---------------------------------------------------------------- prep kernels
__global__ void prep_wc(const float* __restrict__ Wss0,
                        const float* __restrict__ Wvv0)
{
    int k2 = blockIdx.x;      // 0..1311
    int p = threadIdx.x;      // 0..63
    const float C0 = 0.013975424859373686f;       // 1/sqrt(5120)
    const float RS3 = 0.5773502691896258f;        // 1/sqrt(3)
    float vals[2];
    #pragma unroll
    for (int h = 0; h < 2; h++) {
        int k = 2 * k2 + h;
        int u, v, t; decode_k(k, u, v, t);
        float val = 0.f;
        if (t == 0) {
            val = Wss0[(u * 64 + v) * 64 + p];
            if (u != v) val += Wss0[(v * 64 + u) * 64 + p];
            val *= C0;
        } else if (t == 1) {
            val = Wvv0[(u * 32 + v) * 64 + p];
            if (u != v) val += Wvv0[(v * 32 + u) * 64 + p];
            val *= C0 * RS3;
        }
        vals[h] = val;
        if (p == 0) g_puv[k] = (t << 16) | (u << 8) | v;
    }
    g_Wch2[k2 * 64 + p] = __floats2half2_rn(vals[0], vals[1]);
}

__global__ void prep_sv1(const float* __restrict__ Wsv1)
{
    int idx = blockIdx.x * 256 + threadIdx.x;     // 32768
    int qc = idx >> 12;
    int rest = idx & 4095;
    int u2 = rest >> 7;
    int col = rest & 127;
    int v = col >> 2, ql = col & 3;
    int q = qc * 4 + ql;
    g_Wsv1p[idx] = __floats2half2_rn(Wsv1[(2 * u2) * 1024 + v * 32 + q],
                                     Wsv1[(2 * u2 + 1) * 1024 + v * 32 + q]);
}

__global__ void prep_vv2(const float* __restrict__ Wvv2)
{
    int idx = blockIdx.x * 256 + threadIdx.x;     // 8192
    int uc = idx >> 11;
    int rest = idx & 2047;
    int v2 = rest >> 7;
    int col = rest & 127;
    int ul = col >> 4, r = col & 15;
    int u = uc * 8 + ul;
    g_Wvv2p[idx] = __floats2half2_rn(Wvv2[(u * 32 + 2 * v2) * 16 + r],
                                     Wvv2[(u * 32 + 2 * v2 + 1) * 16 + r]);
}

// ------------------------------------------------------------------ z helpers
__device__ __forceinline__ float zval(int k, int node, const float* sv)
{
    int puv = g_puv[k];
    int typ = puv >> 16;
    int u = (puv >> 8) & 255, v = puv & 255;
    if (typ == 0)
        return sv[u * 64 + node] * sv[v * 64 + node];
    if (typ == 1) {
        const float* pa = sv + (64 + 3 * u) * 64 + node;
        const float* pb = sv + (64 + 3 * v) * 64 + node;
        return pa[0] * pb[0] + pa[64] * pb[64] + pa[128] * pb[128];
    }
    return 0.f;
}

__device__ __forceinline__ void build_z(int ck, float* zb, const float* sv, int tid)
{
    int kbase = ck * 64;
    #pragma unroll
    for (int t = 0; t < 8; t++) {
        int idx = tid + t * 256;          // 2048 = 32 k2 x 64 nodes
        int k2l = idx >> 6, node = idx & 63;
        int k0 = kbase + 2 * k2l;
        float z0 = zval(k0, node, sv);
        float z1 = zval(k0 + 1, node, sv);
        *reinterpret_cast<half2*>(zb + k2l * 72 + node) = __floats2half2_rn(z0, z1);
    }
}

__device__ __forceinline__ void stage_w(int ck, float* wb, int tid)
{
    #pragma unroll
    for (int t = 0; t < 2; t++) {
        int idx4 = tid + t * 256;         // 512 uint4 = 2048 words
        int k2l = idx4 >> 4;
        int p4 = (idx4 & 15) * 4;
        uint4 w = *reinterpret_cast<const uint4*>(
            reinterpret_cast<const uint32_t*>(g_Wch2) + (ck * 32 + k2l) * 64 + p4);
        *reinterpret_cast<uint4*>(wb + k2l * 72 + p4) = w;
    }
}

// ------------------------------------------------------------------ main kernel
// 64 nodes/block, 256 threads.
// smem words: sv 10240 | svh2 2304 | vh2 3456 | U 10496 | gv 32  = 26528 (106KB)
#define SMEM_WORDS 26528

__global__ __launch_bounds__(256, 2)
void k_main(const float* __restrict__ x, const float* __restrict__ gates,
            float* __restrict__ out, int B)
{
    extern __shared__ float sm[];
    float* sv   = sm;                 // [160][64] fp32
    float* svh2 = sm + 10240;         // [32 u2][72] half2 words
    float* vh2  = sm + 12544;         // [3j*16 v2][72] half2 words
    float* U    = sm + 16000;         // 10496 words scratch
    float* gv   = sm + 26496;         // 32

    const int tid  = threadIdx.x;
    const int lane = tid & 31;
    const int warp = tid >> 5;
    const int gid  = lane >> 2;
    const int tig  = lane & 3;
    const int node0 = blockIdx.x * 64;

    const int m0   = (warp & 3) * 16;
    const int n0p2 = (warp >> 2) * 32;     // phase-2 N=64 split
    const int n0w  = (warp >> 2) * 64;     // phase-3/4 N=128 split

    if (tid < 32) gv[tid] = tanhf(gates[tid]);
    __syncthreads();

    // ---- Phase 1: load, nonlinearity, feature-major fp32
    for (int idx = tid; idx < 2560; idx += 256) {
        int node = idx / 40;
        int fq = idx - node * 40;
        float4 xv = make_float4(0.f, 0.f, 0.f, 0.f);
        if (node0 + node < B)
            xv = *(const float4*)(x + (size_t)(node0 + node) * 160 + fq * 4);
        float vals[4] = {xv.x, xv.y, xv.z, xv.w};
        #pragma unroll
        for (int jj = 0; jj < 4; jj++) {
            int f = fq * 4 + jj;
            float val = vals[jj];
            if (f < 64) val = tanhf(val);
            else        val *= gv[(f - 64) / 3];
            sv[f * 64 + node] = val;
        }
    }
    __syncthreads();

    // ---- Phase 1b: packed half2 operand copies (s pairs, v-channel pairs)
    for (int idx = tid; idx < 5120; idx += 256) {
        if (idx < 2048) {
            int u2 = idx >> 6, node = idx & 63;
            *reinterpret_cast<half2*>(svh2 + u2 * 72 + node) =
                __floats2half2_rn(sv[(2 * u2) * 64 + node],
                                  sv[(2 * u2 + 1) * 64 + node]);
        } else {
            int j2 = idx - 2048;
            int row = j2 >> 6, node = j2 & 63;   // row = j*16 + v2
            int j = row >> 4, v2 = row & 15;
            *reinterpret_cast<half2*>(vh2 + row * 72 + node) =
                __floats2half2_rn(sv[(64 + 3 * (2 * v2) + j) * 64 + node],
                                  sv[(64 + 3 * (2 * v2 + 1) + j) * 64 + node]);
        }
    }
    __syncthreads();

    // =======================================================================
    // Phase 2: out0 = z[2624] x Wc[2624,64]. fp16 mma, double-buffered chunks.
    //   z buffers at U + buf*2304, w buffers at U + 4608 + buf*2304 (pitch 72)
    // =======================================================================
    float c2a[4][4];
    #pragma unroll
    for (int j = 0; j < 4; j++)
        #pragma unroll
        for (int i = 0; i < 4; i++) c2a[j][i] = 0.f;

    build_z(0, U, sv, tid);
    stage_w(0, U + 4608, tid);
    __syncthreads();

    for (int ck = 0; ck < 41; ck++) {
        int cur = ck & 1;
        float* zb = U + cur * 2304;
        float* wb = U + 4608 + cur * 2304;
        if (ck < 40) {
            build_z(ck + 1, U + (cur ^ 1) * 2304, sv, tid);
            stage_w(ck + 1, U + 4608 + (cur ^ 1) * 2304, tid);
        }
        #pragma unroll
        for (int ks = 0; ks < 4; ks++) {
            int kb2 = ks * 8;
            uint32_t a0 = __float_as_uint(zb[(kb2 + tig) * 72 + m0 + gid]);
            uint32_t a1 = __float_as_uint(zb[(kb2 + tig) * 72 + m0 + gid + 8]);
            uint32_t a2 = __float_as_uint(zb[(kb2 + tig + 4) * 72 + m0 + gid]);
            uint32_t a3 = __float_as_uint(zb[(kb2 + tig + 4) * 72 + m0 + gid + 8]);
            #pragma unroll
            for (int j = 0; j < 4; j++) {
                uint32_t b0 = __float_as_uint(wb[(kb2 + tig) * 72 + n0p2 + j * 8 + gid]);
                uint32_t b1 = __float_as_uint(wb[(kb2 + tig + 4) * 72 + n0p2 + j * 8 + gid]);
                mma_f16(c2a[j], a0, a1, a2, a3, b0, b1);
            }
        }
        __syncthreads();
    }
    // write out0
    {
        int nodeA = node0 + m0 + gid;
        int nodeB = nodeA + 8;
        #pragma unroll
        for (int j = 0; j < 4; j++) {
            int p = n0p2 + j * 8 + 2 * tig;
            if (nodeA < B)
                *(float2*)(out + (size_t)nodeA * 240 + p) = make_float2(c2a[j][0], c2a[j][1]);
            if (nodeB < B)
                *(float2*)(out + (size_t)nodeB * 240 + p) = make_float2(c2a[j][2], c2a[j][3]);
        }
    }

    // =======================================================================
    // Phase 3: out1. 8 q-chunks of 4. GEMM M=64, N=128 (v*4+ql), K=64 (u).
    //   bstage pitch 136 at U (4352 w); A' fp32 pitch 65 aliases U (8320 w)
    // =======================================================================
    const float C1 = 0.022097086912079612f;   // 1/sqrt(2048)
    for (int qc = 0; qc < 8; qc++) {
        #pragma unroll
        for (int t = 0; t < 4; t++) {
            int idx4 = tid + t * 256;       // 1024 uint4
            int u2 = idx4 >> 5, col4 = (idx4 & 31) * 4;
            uint4 w = *reinterpret_cast<const uint4*>(
                reinterpret_cast<const uint32_t*>(g_Wsv1p) + (qc * 32 + u2) * 128 + col4);
            *reinterpret_cast<uint4*>(U + u2 * 136 + col4) = w;
        }
        __syncthreads();
        float c[8][4];
        #pragma unroll
        for (int j = 0; j < 8; j++)
            #pragma unroll
            for (int i = 0; i < 4; i++) c[j][i] = 0.f;
        #pragma unroll
        for (int ks = 0; ks < 4; ks++) {
            int kb2 = ks * 8;
            uint32_t a0 = __float_as_uint(svh2[(kb2 + tig) * 72 + m0 + gid]);
            uint32_t a1 = __float_as_uint(svh2[(kb2 + tig) * 72 + m0 + gid + 8]);
            uint32_t a2 = __float_as_uint(svh2[(kb2 + tig + 4) * 72 + m0 + gid]);
            uint32_t a3 = __float_as_uint(svh2[(kb2 + tig + 4) * 72 + m0 + gid + 8]);
            #pragma unroll
            for (int j = 0; j < 8; j++) {
                int col = n0w + j * 8 + gid;
                uint32_t b0 = __float_as_uint(U[(kb2 + tig) * 136 + col]);
                uint32_t b1 = __float_as_uint(U[(kb2 + tig + 4) * 136 + col]);
                mma_f16(c[j], a0, a1, a2, a3, b0, b1);
            }
        }
        __syncthreads();     // mma done before A' overwrites bstage
        #pragma unroll
        for (int j = 0; j < 8; j++) {
            int col = n0w + j * 8 + 2 * tig;
            U[col * 65 + m0 + gid]           = c[j][0];
            U[(col + 1) * 65 + m0 + gid]     = c[j][1];
            U[col * 65 + m0 + gid + 8]       = c[j][2];
            U[(col + 1) * 65 + m0 + gid + 8] = c[j][3];
        }
        __syncthreads();
        {
            int node = tid & 63, ql = tid >> 6;
            float o0 = 0.f, o1 = 0.f, o2 = 0.f;
            #pragma unroll 8
            for (int v = 0; v < 32; v++) {
                float a = U[(v * 4 + ql) * 65 + node];
                const float* pvv = sv + (64 + 3 * v) * 64 + node;
                o0 += a * pvv[0];
                o1 += a * pvv[64];
                o2 += a * pvv[128];
            }
            int node_g = node0 + node;
            if (node_g < B) {
                float* o = out + (size_t)node_g * 240 + 64 + (qc * 4 + ql) * 3;
                o[0] = C1 * o0; o[1] = C1 * o1; o[2] = C1 * o2;
            }
        }
        __syncthreads();
    }

    // =======================================================================
    // Phase 4: out2. 4 u-chunks x 3 j. GEMM M=64, N=128 (ul*16+r), K=32 (v).
    //   bstage4 pitch 136 at U (2176 w); tvb fp32 pitch 65 at U+2176 (8320 w)
    // =======================================================================
    float S[4][9];
    #pragma unroll
    for (int t = 0; t < 4; t++)
        #pragma unroll
        for (int i = 0; i < 9; i++) S[t][i] = 0.f;

    float* bst4 = U;
    float* tvb  = U + 2176;

    for (int uc = 0; uc < 4; uc++) {
        #pragma unroll
        for (int t = 0; t < 2; t++) {
            int idx4 = tid + t * 256;       // 512 uint4
            int v2 = idx4 >> 5, col4 = (idx4 & 31) * 4;
            uint4 w = *reinterpret_cast<const uint4*>(
                reinterpret_cast<const uint32_t*>(g_Wvv2p) + (uc * 16 + v2) * 128 + col4);
            *reinterpret_cast<uint4*>(bst4 + v2 * 136 + col4) = w;
        }
        __syncthreads();
        for (int j = 0; j < 3; j++) {
            float c[8][4];
            #pragma unroll
            for (int jn = 0; jn < 8; jn++)
                #pragma unroll
                for (int i = 0; i < 4; i++) c[jn][i] = 0.f;
            #pragma unroll
            for (int ks = 0; ks < 2; ks++) {
                int kb2 = ks * 8;
                int arow = j * 16 + kb2;
                uint32_t a0 = __float_as_uint(vh2[(arow + tig) * 72 + m0 + gid]);
                uint32_t a1 = __float_as_uint(vh2[(arow + tig) * 72 + m0 + gid + 8]);
                uint32_t a2 = __float_as_uint(vh2[(arow + tig + 4) * 72 + m0 + gid]);
                uint32_t a3 = __float_as_uint(vh2[(arow + tig + 4) * 72 + m0 + gid + 8]);
                #pragma unroll
                for (int jn = 0; jn < 8; jn++) {
                    int col = n0w + jn * 8 + gid;
                    uint32_t b0 = __float_as_uint(bst4[(kb2 + tig) * 136 + col]);
                    uint32_t b1 = __float_as_uint(bst4[(kb2 + tig + 4) * 136 + col]);
                    mma_f16(c[jn], a0, a1, a2, a3, b0, b1);
                }
            }
            // tvb disjoint from bst4; prev S-accum reads synced at loop end
            #pragma unroll
            for (int jn = 0; jn < 8; jn++) {
                int col = n0w + jn * 8 + 2 * tig;
                tvb[col * 65 + m0 + gid]           = c[jn][0];
                tvb[(col + 1) * 65 + m0 + gid]     = c[jn][1];
                tvb[col * 65 + m0 + gid + 8]       = c[jn][2];
                tvb[(col + 1) * 65 + m0 + gid + 8] = c[jn][3];
            }
            __syncthreads();
            #pragma unroll
            for (int t = 0; t < 4; t++) {
                int it = tid + t * 256;
                int node = it & 63, r = it >> 6;
                #pragma unroll
                for (int ul = 0; ul < 8; ul++) {
                    float tvv = tvb[(ul * 16 + r) * 65 + node];
                    const float* pu_ = sv + (64 + 3 * (uc * 8 + ul)) * 64 + node;
                    S[t][0 + j] += pu_[0]   * tvv;
                    S[t][3 + j] += pu_[64]  * tvv;
                    S[t][6 + j] += pu_[128] * tvv;
                }
            }
            __syncthreads();
        }
    }
    // finalize out2 via CG contraction
    const float C2R2 = (1.f / 32.f) * 0.7071067811865475f;
    const float C2R6 = (1.f / 32.f) * 0.4082482904638630f;
    #pragma unroll
    for (int t = 0; t < 4; t++) {
        int it = tid + t * 256;
        int node = node0 + (it & 63);
        int r = it >> 6;
        if (node < B) {
            float* o = out + (size_t)node * 240 + 160 + r * 5;
            o[0] = C2R2 * (S[t][1] + S[t][3]);                       // S01+S10
            o[1] = C2R2 * (S[t][5] + S[t][7]);                       // S12+S21
            o[2] = C2R6 * (2.f * S[t][8] - S[t][0] - S[t][4]);       // 2S22-S00-S11
            o[3] = C2R2 * (S[t][2] + S[t][6]);                       // S02+S20
            o[4] = C2R2 * (S[t][0] - S[t][4]);                       // S00-S11
        }
    }
}

// ------------------------------------------------------------------- launcher
extern "C" void kernel_launch(void* const* d_in, const int* in_sizes, int n_in,
                              void* d_out, int out_size)
{
    const float* x     = (const float*)d_in[0];
    const float* gates = (const float*)d_in[1];
    const float* Wss0  = (const float*)d_in[2];
    const float* Wsv1  = (const float*)d_in[3];
    const float* Wvv0  = (const float*)d_in[4];
    const float* Wvv2  = (const float*)d_in[5];
    float* out = (float*)d_out;

    int B = in_sizes[0] / 160;

    prep_wc<<<K2PAD, 64>>>(Wss0, Wvv0);
    prep_sv1<<<128, 256>>>(Wsv1);
    prep_vv2<<<32, 256>>>(Wvv2);

    size_t smem_bytes = (size_t)SMEM_WORDS * sizeof(float);   // 106,112 B
    cudaFuncSetAttribute(k_main, cudaFuncAttributeMaxDynamicSharedMemorySize,
                         (int)smem_bytes);
    int grid = (B + 63) / 64;
    k_main<<<grid, 256, smem_bytes>>>(x, gates, out, B);
}

// round 7
// speedup vs baseline: 1.2543x; 1.0084x over previous
#include <cuda_runtime.h>
#include <cuda_fp16.h>
#include <math.h>
#include <stdint.h>

// ----------------------------------------------------------------------------
// NonLinearTSQ: gated tensor-square, fp16 mma.sync (m16n8k16, fp32 accum).
// 3-CTA/SM occupancy build: 73.3KB smem, <=85 regs.
//   in : 64x0e + 32x1o   (160 floats/node)
//   out: 64x0e + 32x1o + 16x2e (240 floats/node), B = 32768
// R6 fix: phase-3 A' packed buffer pitch 33 -> 65 (aliasing bug).
// ----------------------------------------------------------------------------

#define KSS   2080
#define KREAL 2608
#define KPAD  2624
#define K2PAD 1312          // KPAD/2, 41 chunks of 32 half2-rows

__device__ __align__(16) half2 g_Wch2[K2PAD * 64];   // out0 weights, k-paired
__device__ __align__(16) half2 g_Wsv1p[32768];       // [qc][u2][v*4+ql]
__device__ __align__(16) half2 g_Wvv2p[8192];        // [uc][v2][ul*16+r]
__device__ int g_puv[KPAD];                          // (type<<16)|(u<<8)|v

// ---------------------------------------------------------------- helpers
__device__ __forceinline__ void decode_k(int k, int& u, int& v, int& t) {
    u = 0; v = 0; t = 2;
    if (k < KSS) {
        int rem = k, row = 64;
        while (rem >= row) { rem -= row; row--; }
        u = 64 - row; v = u + rem; t = 0;
    } else if (k < KREAL) {
        int rem = k - KSS, row = 32;
        while (rem >= row) { rem -= row; row--; }
        u = 32 - row; v = u + rem; t = 1;
    }
}

__device__ __forceinline__ void mma_f16(float* c,
                                        uint32_t a0, uint32_t a1,
                                        uint32_t a2, uint32_t a3,
                                        uint32_t b0, uint32_t b1) {
    asm volatile(
        "mma.sync.aligned.m16n8k16.row.col.f32.f16.f16.f32 "
        "{%0,%1,%2,%3}, {%4,%5,%6,%7}, {%8,%9}, {%0,%1,%2,%3};"
        : "+f"(c[0]), "+f"(c[1]), "+f"(c[2]), "+f"(c[3])
        : "r"(a0), "r"(a1), "r"(a2), "r"(a3), "r"(b0), "r"(b1));
}

__device__ __forceinline__ float h2_get(float w, int sel) {
    half2 h = *reinterpret_cast<half2*>(&w);
    return sel ? __high2float(h) : __low2float(h);
}

// ---------------------------------------------------------------- prep kernels
__global__ void prep_wc(const float* __restrict__ Wss0,
                        const float* __restrict__ Wvv0)
{
    int k2 = blockIdx.x;      // 0..1311
    int p = threadIdx.x;      // 0..63
    const float C0 = 0.013975424859373686f;       // 1/sqrt(5120)
    const float RS3 = 0.5773502691896258f;        // 1/sqrt(3)
    float vals[2];
    #pragma unroll
    for (int h = 0; h < 2; h++) {
        int k = 2 * k2 + h;
        int u, v, t; decode_k(k, u, v, t);
        float val = 0.f;
        if (t == 0) {
            val = Wss0[(u * 64 + v) * 64 + p];
            if (u != v) val += Wss0[(v * 64 + u) * 64 + p];
            val *= C0;
        } else if (t == 1) {
            val = Wvv0[(u * 32 + v) * 64 + p];
            if (u != v) val += Wvv0[(v * 32 + u) * 64 + p];
            val *= C0 * RS3;
        }
        vals[h] = val;
        if (p == 0) g_puv[k] = (t << 16) | (u << 8) | v;
    }
    g_Wch2[k2 * 64 + p] = __floats2half2_rn(vals[0], vals[1]);
}

__global__ void prep_sv1(const float* __restrict__ Wsv1)
{
    int idx = blockIdx.x * 256 + threadIdx.x;     // 32768
    int qc = idx >> 12;
    int rest = idx & 4095;
    int u2 = rest >> 7;
    int col = rest & 127;
    int v = col >> 2, ql = col & 3;
    int q = qc * 4 + ql;
    g_Wsv1p[idx] = __floats2half2_rn(Wsv1[(2 * u2) * 1024 + v * 32 + q],
                                     Wsv1[(2 * u2 + 1) * 1024 + v * 32 + q]);
}

__global__ void prep_vv2(const float* __restrict__ Wvv2)
{
    int idx = blockIdx.x * 256 + threadIdx.x;     // 8192
    int uc = idx >> 11;
    int rest = idx & 2047;
    int v2 = rest >> 7;
    int col = rest & 127;
    int ul = col >> 4, r = col & 15;
    int u = uc * 8 + ul;
    g_Wvv2p[idx] = __floats2half2_rn(Wvv2[(u * 32 + 2 * v2) * 16 + r],
                                     Wvv2[(u * 32 + 2 * v2 + 1) * 16 + r]);
}

// ------------------------------------------------------------------ z helpers
// s in packed half2 (svh2[u2*72+node] = (s_{2u2}, s_{2u2+1})); v in fp32 svv.
__device__ __forceinline__ float zval(int k, int node,
                                      const float* svh2, const float* svv)
{
    int puv = g_puv[k];
    int typ = puv >> 16;
    int u = (puv >> 8) & 255, v = puv & 255;
    if (typ == 0) {
        float su = h2_get(svh2[(u >> 1) * 72 + node], u & 1);
        float sw = h2_get(svh2[(v >> 1) * 72 + node], v & 1);
        return su * sw;
    }
    if (typ == 1) {
        const float* pa = svv + (3 * u) * 64 + node;
        const float* pb = svv + (3 * v) * 64 + node;
        return pa[0] * pb[0] + pa[64] * pb[64] + pa[128] * pb[128];
    }
    return 0.f;
}

__device__ __forceinline__ void build_z(int ck, float* zb,
                                        const float* svh2, const float* svv, int tid)
{
    int kbase = ck * 64;
    #pragma unroll
    for (int t = 0; t < 8; t++) {
        int idx = tid + t * 256;          // 2048 = 32 k2 x 64 nodes
        int k2l = idx >> 6, node = idx & 63;
        int k0 = kbase + 2 * k2l;
        float z0 = zval(k0, node, svh2, svv);
        float z1 = zval(k0 + 1, node, svh2, svv);
        *reinterpret_cast<half2*>(zb + k2l * 72 + node) = __floats2half2_rn(z0, z1);
    }
}

__device__ __forceinline__ void stage_w(int ck, float* wb, int tid)
{
    #pragma unroll
    for (int t = 0; t < 2; t++) {
        int idx4 = tid + t * 256;         // 512 uint4 = 2048 words
        int k2l = idx4 >> 4;
        int p4 = (idx4 & 15) * 4;
        uint4 w = *reinterpret_cast<const uint4*>(
            reinterpret_cast<const uint32_t*>(g_Wch2) + (ck * 32 + k2l) * 64 + p4);
        *reinterpret_cast<uint4*>(wb + k2l * 72 + p4) = w;
    }
}

// ------------------------------------------------------------------ main kernel
// 64 nodes/block, 256 threads, 3 CTAs/SM.
// smem words: svh2 2304 | svv 6144 | U 9856 | gv 32 = 18336 (73,344 B)
#define U_FLOATS    9856
#define SMEM_WORDS  18336

__global__ __launch_bounds__(256, 3)
void k_main(const float* __restrict__ x, const float* __restrict__ gates,
            float* __restrict__ out, int B)
{
    extern __shared__ float sm[];
    float* svh2 = sm;                 // [32 u2][72] half2 words
    float* svv  = sm + 2304;          // [96 rows=3v+j][64] fp32
    float* U    = sm + 8448;          // 9856-word scratch union
    float* gv   = sm + 18304;         // 32

    const int tid  = threadIdx.x;
    const int lane = tid & 31;
    const int warp = tid >> 5;
    const int gid  = lane >> 2;
    const int tig  = lane & 3;
    const int node0 = blockIdx.x * 64;

    const int m0   = (warp & 3) * 16;
    const int n0p2 = (warp >> 2) * 32;     // phase-2 N=64 split
    const int n0w  = (warp >> 2) * 64;     // phase-3/4 N=128 split

    if (tid < 32) gv[tid] = tanhf(gates[tid]);
    __syncthreads();

    // ---- Phase 1: load, nonlinearity. s -> packed half2, v -> fp32.
    for (int idx = tid; idx < 2560; idx += 256) {
        int node = idx / 40;
        int fq = idx - node * 40;
        float4 xv = make_float4(0.f, 0.f, 0.f, 0.f);
        if (node0 + node < B)
            xv = *(const float4*)(x + (size_t)(node0 + node) * 160 + fq * 4);
        if (fq < 16) {
            float t0 = tanhf(xv.x), t1 = tanhf(xv.y);
            float t2 = tanhf(xv.z), t3 = tanhf(xv.w);
            *reinterpret_cast<half2*>(svh2 + (fq * 2) * 72 + node) =
                __floats2half2_rn(t0, t1);
            *reinterpret_cast<half2*>(svh2 + (fq * 2 + 1) * 72 + node) =
                __floats2half2_rn(t2, t3);
        } else {
            float vals[4] = {xv.x, xv.y, xv.z, xv.w};
            #pragma unroll
            for (int jj = 0; jj < 4; jj++) {
                int r = (fq - 16) * 4 + jj;         // 0..95 = 3v+j
                svv[r * 64 + node] = vals[jj] * gv[r / 3];
            }
        }
    }
    __syncthreads();

    // =======================================================================
    // Phase 2: out0 = z[2624] x Wc[2624,64]. Double-buffered chunks.
    //   z: U+{0,2304}; w: U+4608+{0,2304}  (pitch 72)
    // =======================================================================
    float c2a[4][4];
    #pragma unroll
    for (int j = 0; j < 4; j++)
        #pragma unroll
        for (int i = 0; i < 4; i++) c2a[j][i] = 0.f;

    build_z(0, U, svh2, svv, tid);
    stage_w(0, U + 4608, tid);
    __syncthreads();

    for (int ck = 0; ck < 41; ck++) {
        int cur = ck & 1;
        float* zb = U + cur * 2304;
        float* wb = U + 4608 + cur * 2304;
        if (ck < 40) {
            build_z(ck + 1, U + (cur ^ 1) * 2304, svh2, svv, tid);
            stage_w(ck + 1, U + 4608 + (cur ^ 1) * 2304, tid);
        }
        #pragma unroll
        for (int ks = 0; ks < 4; ks++) {
            int kb2 = ks * 8;
            uint32_t a0 = __float_as_uint(zb[(kb2 + tig) * 72 + m0 + gid]);
            uint32_t a1 = __float_as_uint(zb[(kb2 + tig) * 72 + m0 + gid + 8]);
            uint32_t a2 = __float_as_uint(zb[(kb2 + tig + 4) * 72 + m0 + gid]);
            uint32_t a3 = __float_as_uint(zb[(kb2 + tig + 4) * 72 + m0 + gid + 8]);
            #pragma unroll
            for (int j = 0; j < 4; j++) {
                uint32_t b0 = __float_as_uint(wb[(kb2 + tig) * 72 + n0p2 + j * 8 + gid]);
                uint32_t b1 = __float_as_uint(wb[(kb2 + tig + 4) * 72 + n0p2 + j * 8 + gid]);
                mma_f16(c2a[j], a0, a1, a2, a3, b0, b1);
            }
        }
        __syncthreads();
    }
    // write out0
    {
        int nodeA = node0 + m0 + gid;
        int nodeB = nodeA + 8;
        #pragma unroll
        for (int j = 0; j < 4; j++) {
            int p = n0p2 + j * 8 + 2 * tig;
            if (nodeA < B)
                *(float2*)(out + (size_t)nodeA * 240 + p) = make_float2(c2a[j][0], c2a[j][1]);
            if (nodeB < B)
                *(float2*)(out + (size_t)nodeB * 240 + p) = make_float2(c2a[j][2], c2a[j][3]);
        }
    }

    // =======================================================================
    // Phase 3: out1. 8 q-chunks of 4. GEMM M=64, N=128 (v*4+ql), K=64 (u).
    //   bstage: U[0..4352) pitch 136. A'h (packed half2): U+4352, [node][65].
    //   mma in 2 passes of 4 n-tiles (reg cap).
    // =======================================================================
    const float C1 = 0.022097086912079612f;   // 1/sqrt(2048)
    float* Ah = U + 4352;                     // 64 nodes x pitch 65 = 4160 w
    for (int qc = 0; qc < 8; qc++) {
        #pragma unroll
        for (int t = 0; t < 4; t++) {
            int idx4 = tid + t * 256;       // 1024 uint4
            int u2 = idx4 >> 5, col4 = (idx4 & 31) * 4;
            uint4 w = *reinterpret_cast<const uint4*>(
                reinterpret_cast<const uint32_t*>(g_Wsv1p) + (qc * 32 + u2) * 128 + col4);
            *reinterpret_cast<uint4*>(U + u2 * 136 + col4) = w;
        }
        __syncthreads();
        #pragma unroll
        for (int pass = 0; pass < 2; pass++) {
            float c[4][4];
            #pragma unroll
            for (int j = 0; j < 4; j++)
                #pragma unroll
                for (int i = 0; i < 4; i++) c[j][i] = 0.f;
            #pragma unroll
            for (int ks = 0; ks < 4; ks++) {
                int kb2 = ks * 8;
                uint32_t a0 = __float_as_uint(svh2[(kb2 + tig) * 72 + m0 + gid]);
                uint32_t a1 = __float_as_uint(svh2[(kb2 + tig) * 72 + m0 + gid + 8]);
                uint32_t a2 = __float_as_uint(svh2[(kb2 + tig + 4) * 72 + m0 + gid]);
                uint32_t a3 = __float_as_uint(svh2[(kb2 + tig + 4) * 72 + m0 + gid + 8]);
                #pragma unroll
                for (int j = 0; j < 4; j++) {
                    int col = n0w + (pass * 4 + j) * 8 + gid;
                    uint32_t b0 = __float_as_uint(U[(kb2 + tig) * 136 + col]);
                    uint32_t b1 = __float_as_uint(U[(kb2 + tig + 4) * 136 + col]);
                    mma_f16(c[j], a0, a1, a2, a3, b0, b1);
                }
            }
            // write A'h packed: [node][col2], pitch 65 (disjoint from bstage)
            #pragma unroll
            for (int j = 0; j < 4; j++) {
                int col2 = (n0w + (pass * 4 + j) * 8 + 2 * tig) >> 1;
                *reinterpret_cast<half2*>(Ah + (m0 + gid) * 65 + col2) =
                    __floats2half2_rn(c[j][0], c[j][1]);
                *reinterpret_cast<half2*>(Ah + (m0 + gid + 8) * 65 + col2) =
                    __floats2half2_rn(c[j][2], c[j][3]);
            }
        }
        __syncthreads();
        // epilogue: 256 items (node, ql)
        {
            int node = tid & 63, ql = tid >> 6;
            int hsel = ql & 1;
            float o0 = 0.f, o1 = 0.f, o2 = 0.f;
            #pragma unroll 8
            for (int v = 0; v < 32; v++) {
                float a = h2_get(Ah[node * 65 + v * 2 + (ql >> 1)], hsel);
                const float* pvv = svv + (3 * v) * 64 + node;
                o0 += a * pvv[0];
                o1 += a * pvv[64];
                o2 += a * pvv[128];
            }
            int node_g = node0 + node;
            if (node_g < B) {
                float* o = out + (size_t)node_g * 240 + 64 + (qc * 4 + ql) * 3;
                o[0] = C1 * o0; o[1] = C1 * o1; o[2] = C1 * o2;
            }
        }
        __syncthreads();
    }

    // =======================================================================
    // Phase 4: out2. 4 u-chunks x 3 j. GEMM M=64, N=128 (ul*16+r), K=32 (v).
    //   bst4: U[0..2176); tvbh packed half2: U+2176 [node][65];
    //   vh2: U+6336 [48 rows=j*16+v2][72].
    // =======================================================================
    float* tvbh = U + 2176;
    float* vh2  = U + 6336;

    // build vh2 (after phase-3 epilogue barrier; overlaps old A'h region)
    for (int idx = tid; idx < 3072; idx += 256) {
        int row = idx >> 6, node = idx & 63;     // row = j*16 + v2
        int j = row >> 4, v2 = row & 15;
        *reinterpret_cast<half2*>(vh2 + row * 72 + node) =
            __floats2half2_rn(svv[(3 * (2 * v2) + j) * 64 + node],
                              svv[(3 * (2 * v2 + 1) + j) * 64 + node]);
    }
    __syncthreads();

    float S[4][9];
    #pragma unroll
    for (int t = 0; t < 4; t++)
        #pragma unroll
        for (int i = 0; i < 9; i++) S[t][i] = 0.f;

    for (int uc = 0; uc < 4; uc++) {
        #pragma unroll
        for (int t = 0; t < 2; t++) {
            int idx4 = tid + t * 256;       // 512 uint4
            int v2 = idx4 >> 5, col4 = (idx4 & 31) * 4;
            uint4 w = *reinterpret_cast<const uint4*>(
                reinterpret_cast<const uint32_t*>(g_Wvv2p) + (uc * 16 + v2) * 128 + col4);
            *reinterpret_cast<uint4*>(U + v2 * 136 + col4) = w;
        }
        __syncthreads();
        for (int j = 0; j < 3; j++) {
            #pragma unroll
            for (int pass = 0; pass < 2; pass++) {
                float c[4][4];
                #pragma unroll
                for (int jn = 0; jn < 4; jn++)
                    #pragma unroll
                    for (int i = 0; i < 4; i++) c[jn][i] = 0.f;
                #pragma unroll
                for (int ks = 0; ks < 2; ks++) {
                    int kb2 = ks * 8;
                    int arow = j * 16 + kb2;
                    uint32_t a0 = __float_as_uint(vh2[(arow + tig) * 72 + m0 + gid]);
                    uint32_t a1 = __float_as_uint(vh2[(arow + tig) * 72 + m0 + gid + 8]);
                    uint32_t a2 = __float_as_uint(vh2[(arow + tig + 4) * 72 + m0 + gid]);
                    uint32_t a3 = __float_as_uint(vh2[(arow + tig + 4) * 72 + m0 + gid + 8]);
                    #pragma unroll
                    for (int jn = 0; jn < 4; jn++) {
                        int col = n0w + (pass * 4 + jn) * 8 + gid;
                        uint32_t b0 = __float_as_uint(U[(kb2 + tig) * 136 + col]);
                        uint32_t b1 = __float_as_uint(U[(kb2 + tig + 4) * 136 + col]);
                        mma_f16(c[jn], a0, a1, a2, a3, b0, b1);
                    }
                }
                // write tvbh packed: [node][col2]; prev S-accum synced below
                #pragma unroll
                for (int jn = 0; jn < 4; jn++) {
                    int col2 = (n0w + (pass * 4 + jn) * 8 + 2 * tig) >> 1;
                    *reinterpret_cast<half2*>(tvbh + (m0 + gid) * 65 + col2) =
                        __floats2half2_rn(c[jn][0], c[jn][1]);
                    *reinterpret_cast<half2*>(tvbh + (m0 + gid + 8) * 65 + col2) =
                        __floats2half2_rn(c[jn][2], c[jn][3]);
                }
            }
            __syncthreads();
            // S accumulation: 1024 items (node, r)
            #pragma unroll
            for (int t = 0; t < 4; t++) {
                int it = tid + t * 256;
                int node = it & 63, r = it >> 6;
                int hsel = r & 1;
                #pragma unroll
                for (int ul = 0; ul < 8; ul++) {
                    float tvv = h2_get(tvbh[node * 65 + ul * 8 + (r >> 1)], hsel);
                    const float* pu_ = svv + (3 * (uc * 8 + ul)) * 64 + node;
                    S[t][0 + j] += pu_[0]   * tvv;
                    S[t][3 + j] += pu_[64]  * tvv;
                    S[t][6 + j] += pu_[128] * tvv;
                }
            }
            __syncthreads();
        }
    }
    // finalize out2 via CG contraction
    const float C2R2 = (1.f / 32.f) * 0.7071067811865475f;
    const float C2R6 = (1.f / 32.f) * 0.4082482904638630f;
    #pragma unroll
    for (int t = 0; t < 4; t++) {
        int it = tid + t * 256;
        int node = node0 + (it & 63);
        int r = it >> 6;
        if (node < B) {
            float* o = out + (size_t)node * 240 + 160 + r * 5;
            o[0] = C2R2 * (S[t][1] + S[t][3]);                       // S01+S10
            o[1] = C2R2 * (S[t][5] + S[t][7]);                       // S12+S21
            o[2] = C2R6 * (2.f * S[t][8] - S[t][0] - S[t][4]);       // 2S22-S00-S11
            o[3] = C2R2 * (S[t][2] + S[t][6]);                       // S02+S20
            o[4] = C2R2 * (S[t][0] - S[t][4]);                       // S00-S11
        }
    }
}

// ------------------------------------------------------------------- launcher
extern "C" void kernel_launch(void* const* d_in, const int* in_sizes, int n_in,
                              void* d_out, int out_size)
{
    const float* x     = (const float*)d_in[0];
    const float* gates = (const float*)d_in[1];
    const float* Wss0  = (const float*)d_in[2];
    const float* Wsv1  = (const float*)d_in[3];
    const float* Wvv0  = (const float*)d_in[4];
    const float* Wvv2  = (const float*)d_in[5];
    float* out = (float*)d_out;

    int B = in_sizes[0] / 160;

    prep_wc<<<K2PAD, 64>>>(Wss0, Wvv0);
    prep_sv1<<<128, 256>>>(Wsv1);
    prep_vv2<<<32, 256>>>(Wvv2);

    size_t smem_bytes = (size_t)SMEM_WORDS * sizeof(float);   // 73,344 B
    cudaFuncSetAttribute(k_main, cudaFuncAttributeMaxDynamicSharedMemorySize,
                         (int)smem_bytes);
    int grid = (B + 63) / 64;
    k_main<<<grid, 256, smem_bytes>>>(x, gates, out, B);
}

// round 8
// speedup vs baseline: 1.2669x; 1.0100x over previous
#include <cuda_runtime.h>
#include <cuda_fp16.h>
#include <math.h>
#include <stdint.h>

// ----------------------------------------------------------------------------
// NonLinearTSQ: gated tensor-square, fp16 mma.sync (m16n8k16, fp32 accum).
// R8: descriptor-driven half2 z-build, mma B-operands direct from global
// (no smem weight staging), persistent vA, 64.6KB smem, 3 CTAs/SM.
//   in : 64x0e + 32x1o (160 f/node); out: 64x0e+32x1o+16x2e (240), B=32768
// ----------------------------------------------------------------------------

#define KSS   2080
#define KREAL 2608
#define KPAD  2624
#define K2PAD 1312          // 41 chunks of 32 k2 (z-pairs)

__device__ __align__(16) half2 g_Wch2[K2PAD * 64];   // [k2][p] k-paired
__device__ __align__(16) half2 g_Wsv1p[32768];       // [qc][u2][v*4+ql]
__device__ __align__(16) half2 g_Wvv2p[8192];        // [uc][v2][ul*16+r]
__device__ int g_desc[K2PAD];                        // z-pair descriptors

// ---------------------------------------------------------------- helpers
__device__ __forceinline__ void decode_k(int k, int& u, int& v, int& t) {
    u = 0; v = 0; t = 2;
    if (k < KSS) {
        int rem = k, row = 64;
        while (rem >= row) { rem -= row; row--; }
        u = 64 - row; v = u + rem; t = 0;
    } else if (k < KREAL) {
        int rem = k - KSS, row = 32;
        while (rem >= row) { rem -= row; row--; }
        u = 32 - row; v = u + rem; t = 1;
    }
}

__device__ __forceinline__ void mma_f16(float* c,
                                        uint32_t a0, uint32_t a1,
                                        uint32_t a2, uint32_t a3,
                                        uint32_t b0, uint32_t b1) {
    asm volatile(
        "mma.sync.aligned.m16n8k16.row.col.f32.f16.f16.f32 "
        "{%0,%1,%2,%3}, {%4,%5,%6,%7}, {%8,%9}, {%0,%1,%2,%3};"
        : "+f"(c[0]), "+f"(c[1]), "+f"(c[2]), "+f"(c[3])
        : "r"(a0), "r"(a1), "r"(a2), "r"(a3), "r"(b0), "r"(b1));
}

__device__ __forceinline__ uint32_t prmt32(uint32_t a, uint32_t b, uint32_t s) {
    uint32_t r;
    asm("prmt.b32 %0,%1,%2,%3;" : "=r"(r) : "r"(a), "r"(b), "r"(s));
    return r;
}
__device__ __forceinline__ uint32_t hmul2u(uint32_t a, uint32_t b) {
    uint32_t r;
    asm("mul.f16x2 %0,%1,%2;" : "=r"(r) : "r"(a), "r"(b));
    return r;
}
__device__ __forceinline__ uint32_t hfma2u(uint32_t a, uint32_t b, uint32_t c) {
    uint32_t r;
    asm("fma.rn.f16x2 %0,%1,%2,%3;" : "=r"(r) : "r"(a), "r"(b), "r"(c));
    return r;
}
__device__ __forceinline__ float h2_get(float w, int sel) {
    half2 h = *reinterpret_cast<half2*>(&w);
    return sel ? __high2float(h) : __low2float(h);
}
__device__ __forceinline__ __half sgeth(const uint32_t* sA, int a, int node) {
    uint32_t w = sA[(a >> 1) * 72 + node];
    __half2 h = *reinterpret_cast<__half2*>(&w);
    return (a & 1) ? __high2half(h) : __low2half(h);
}
__device__ __forceinline__ __half vgeth(const uint32_t* vA, int a, int j, int node) {
    uint32_t w = vA[(j * 16 + (a >> 1)) * 72 + node];
    __half2 h = *reinterpret_cast<__half2*>(&w);
    return (a & 1) ? __high2half(h) : __low2half(h);
}

// ---------------------------------------------------------------- prep kernels
__global__ void prep_desc()
{
    int k2 = blockIdx.x * 256 + threadIdx.x;
    if (k2 >= K2PAD) return;
    int u0, v0, t0, u1, v1, t1;
    decode_k(2 * k2, u0, v0, t0);
    decode_k(2 * k2 + 1, u1, v1, t1);
    int d;
    if (t0 == 2) {
        d = 5 << 28;                                     // zero padding
    } else if (t0 == t1 && u0 == u1 && v1 == v0 + 1) {
        int mode = ((t0 == 0) ? 0 : 2) + (v0 & 1);        // fast paths
        d = (mode << 28) | (u0 << 8) | v0;
    } else {
        d = (4 << 28) | ((t0 & 1) << 24) |                // generic
            (u0 << 18) | (v0 << 12) | (u1 << 6) | v1;
    }
    g_desc[k2] = d;
}

__global__ void prep_wc(const float* __restrict__ Wss0,
                        const float* __restrict__ Wvv0)
{
    int k2 = blockIdx.x;      // 0..1311
    int p = threadIdx.x;      // 0..63
    const float C0 = 0.013975424859373686f;       // 1/sqrt(5120)
    const float RS3 = 0.5773502691896258f;        // 1/sqrt(3)
    float vals[2];
    #pragma unroll
    for (int h = 0; h < 2; h++) {
        int k = 2 * k2 + h;
        int u, v, t; decode_k(k, u, v, t);
        float val = 0.f;
        if (t == 0) {
            val = Wss0[(u * 64 + v) * 64 + p];
            if (u != v) val += Wss0[(v * 64 + u) * 64 + p];
            val *= C0;
        } else if (t == 1) {
            val = Wvv0[(u * 32 + v) * 64 + p];
            if (u != v) val += Wvv0[(v * 32 + u) * 64 + p];
            val *= C0 * RS3;
        }
        vals[h] = val;
    }
    g_Wch2[k2 * 64 + p] = __floats2half2_rn(vals[0], vals[1]);
}

__global__ void prep_sv1(const float* __restrict__ Wsv1)
{
    int idx = blockIdx.x * 256 + threadIdx.x;     // 32768
    int qc = idx >> 12;
    int rest = idx & 4095;
    int u2 = rest >> 7;
    int col = rest & 127;
    int v = col >> 2, ql = col & 3;
    int q = qc * 4 + ql;
    g_Wsv1p[idx] = __floats2half2_rn(Wsv1[(2 * u2) * 1024 + v * 32 + q],
                                     Wsv1[(2 * u2 + 1) * 1024 + v * 32 + q]);
}

__global__ void prep_vv2(const float* __restrict__ Wvv2)
{
    int idx = blockIdx.x * 256 + threadIdx.x;     // 8192
    int uc = idx >> 11;
    int rest = idx & 2047;
    int v2 = rest >> 7;
    int col = rest & 127;
    int ul = col >> 4, r = col & 15;
    int u = uc * 8 + ul;
    g_Wvv2p[idx] = __floats2half2_rn(Wvv2[(u * 32 + 2 * v2) * 16 + r],
                                     Wvv2[(u * 32 + 2 * v2 + 1) * 16 + r]);
}

// ------------------------------------------------------------------ z build
// sA[u2][72]: (s_2u2, s_2u2+1) per node; vA[j*16+v2][72]: (v_2v2[j], v_2v2+1[j])
__device__ __forceinline__ void build_z(int ck, uint32_t* zb,
                                        const uint32_t* sA, const uint32_t* vA,
                                        int tid)
{
    int kb = ck * 32;
    #pragma unroll
    for (int t = 0; t < 8; t++) {
        int idx = tid + t * 256;           // 2048 = 32 k2 x 64 nodes
        int k2l = idx >> 6, node = idx & 63;
        int d = g_desc[kb + k2l];          // warp-uniform
        int mode = (unsigned)d >> 28;
        uint32_t z2 = 0;
        if (mode <= 1) {                   // ss, pairs (u,v),(u,v+1)
            int u = (d >> 8) & 255, v = d & 255;
            uint32_t uw = sA[(u >> 1) * 72 + node];
            uint32_t us = (u & 1) ? prmt32(uw, uw, 0x3232)
                                  : prmt32(uw, uw, 0x1010);
            uint32_t pw;
            if (mode == 0) pw = sA[(v >> 1) * 72 + node];
            else pw = prmt32(sA[(v >> 1) * 72 + node],
                             sA[((v + 1) >> 1) * 72 + node], 0x5432);
            z2 = hmul2u(us, pw);
        } else if (mode <= 3) {            // vv dot, pairs (u,v),(u,v+1)
            int u = (d >> 8) & 255, v = d & 255;
            #pragma unroll
            for (int j = 0; j < 3; j++) {
                uint32_t uw = vA[(j * 16 + (u >> 1)) * 72 + node];
                uint32_t us = (u & 1) ? prmt32(uw, uw, 0x3232)
                                      : prmt32(uw, uw, 0x1010);
                uint32_t pw;
                if (mode == 2) pw = vA[(j * 16 + (v >> 1)) * 72 + node];
                else pw = prmt32(vA[(j * 16 + (v >> 1)) * 72 + node],
                                 vA[(j * 16 + ((v + 1) >> 1)) * 72 + node],
                                 0x5432);
                z2 = (j == 0) ? hmul2u(us, pw) : hfma2u(us, pw, z2);
            }
        } else if (mode == 4) {            // generic (row-crossing)
            int tt = (d >> 24) & 1;
            int u0 = (d >> 18) & 63, v0 = (d >> 12) & 63;
            int u1 = (d >> 6) & 63,  v1 = d & 63;
            __half z0, z1;
            if (tt == 0) {
                z0 = __hmul(sgeth(sA, u0, node), sgeth(sA, v0, node));
                z1 = __hmul(sgeth(sA, u1, node), sgeth(sA, v1, node));
            } else {
                float a0 = 0.f, a1 = 0.f;
                #pragma unroll
                for (int j = 0; j < 3; j++) {
                    a0 += __half2float(vgeth(vA, u0, j, node)) *
                          __half2float(vgeth(vA, v0, j, node));
                    a1 += __half2float(vgeth(vA, u1, j, node)) *
                          __half2float(vgeth(vA, v1, j, node));
                }
                z0 = __float2half(a0); z1 = __float2half(a1);
            }
            __half2 p = __halves2half2(z0, z1);
            z2 = *reinterpret_cast<uint32_t*>(&p);
        }
        zb[k2l * 72 + node] = z2;
    }
}

// ------------------------------------------------------------------ main kernel
// 64 nodes/block, 256 threads, 3 CTAs/SM.
// smem words: sA 2304 | svv 6144 | vA 3456 | U 4608 | gv 32 = 16544 (66,176 B)
#define SMEM_WORDS 16544

__global__ __launch_bounds__(256, 3)
void k_main(const float* __restrict__ x, const float* __restrict__ gates,
            float* __restrict__ out, int B)
{
    extern __shared__ float sm[];
    uint32_t* sA = reinterpret_cast<uint32_t*>(sm);       // [32][72]
    float* svv   = sm + 2304;                             // [96 rows=3v+j][64]
    uint32_t* vA = reinterpret_cast<uint32_t*>(sm + 8448);// [48][72]
    float* U     = sm + 11904;                            // 4608 scratch
    float* gv    = sm + 16512;                            // 32

    const int tid  = threadIdx.x;
    const int lane = tid & 31;
    const int warp = tid >> 5;
    const int gid  = lane >> 2;
    const int tig  = lane & 3;
    const int node0 = blockIdx.x * 64;

    const int m0   = (warp & 3) * 16;
    const int n0p2 = (warp >> 2) * 32;     // phase-2 N=64 split
    const int n0w  = (warp >> 2) * 64;     // phase-3/4 N=128 split

    if (tid < 32) gv[tid] = tanhf(gates[tid]);
    __syncthreads();

    // ---- Phase 1: load, nonlinearity. s -> sA (half2 pairs), v -> svv fp32.
    for (int idx = tid; idx < 2560; idx += 256) {
        int node = idx / 40;
        int fq = idx - node * 40;
        float4 xv = make_float4(0.f, 0.f, 0.f, 0.f);
        if (node0 + node < B)
            xv = *(const float4*)(x + (size_t)(node0 + node) * 160 + fq * 4);
        if (fq < 16) {
            __half2 h0 = __floats2half2_rn(tanhf(xv.x), tanhf(xv.y));
            __half2 h1 = __floats2half2_rn(tanhf(xv.z), tanhf(xv.w));
            sA[(fq * 2) * 72 + node]     = *reinterpret_cast<uint32_t*>(&h0);
            sA[(fq * 2 + 1) * 72 + node] = *reinterpret_cast<uint32_t*>(&h1);
        } else {
            float vals[4] = {xv.x, xv.y, xv.z, xv.w};
            #pragma unroll
            for (int jj = 0; jj < 4; jj++) {
                int r = (fq - 16) * 4 + jj;         // 0..95 = 3v+j
                svv[r * 64 + node] = vals[jj] * gv[r / 3];
            }
        }
    }
    __syncthreads();

    // ---- Phase 1b: vA from svv (v-channel pairs per component)
    for (int idx = tid; idx < 3072; idx += 256) {
        int row = idx >> 6, node = idx & 63;      // row = j*16 + v2
        int j = row >> 4, v2 = row & 15;
        __half2 h = __floats2half2_rn(svv[(6 * v2 + j) * 64 + node],
                                      svv[(6 * v2 + 3 + j) * 64 + node]);
        vA[row * 72 + node] = *reinterpret_cast<uint32_t*>(&h);
    }
    __syncthreads();

    // =======================================================================
    // Phase 2: out0 = z[2624] x Wc[2624,64]. Double-buffered z; B from global.
    // =======================================================================
    float c2a[4][4];
    #pragma unroll
    for (int j = 0; j < 4; j++)
        #pragma unroll
        for (int i = 0; i < 4; i++) c2a[j][i] = 0.f;

    const uint32_t* Wg = reinterpret_cast<const uint32_t*>(g_Wch2);
    uint32_t* Uz = reinterpret_cast<uint32_t*>(U);

    build_z(0, Uz, sA, vA, tid);
    __syncthreads();

    for (int ck = 0; ck < 41; ck++) {
        uint32_t* zb = Uz + (ck & 1) * 2304;
        if (ck < 40)
            build_z(ck + 1, Uz + ((ck & 1) ^ 1) * 2304, sA, vA, tid);
        #pragma unroll
        for (int ks = 0; ks < 4; ks++) {
            int kb2 = ks * 8;
            uint32_t a0 = zb[(kb2 + tig) * 72 + m0 + gid];
            uint32_t a1 = zb[(kb2 + tig) * 72 + m0 + gid + 8];
            uint32_t a2 = zb[(kb2 + tig + 4) * 72 + m0 + gid];
            uint32_t a3 = zb[(kb2 + tig + 4) * 72 + m0 + gid + 8];
            #pragma unroll
            for (int j = 0; j < 4; j++) {
                uint32_t b0 = __ldg(Wg + (size_t)(ck * 32 + kb2 + tig) * 64
                                       + n0p2 + j * 8 + gid);
                uint32_t b1 = __ldg(Wg + (size_t)(ck * 32 + kb2 + tig + 4) * 64
                                       + n0p2 + j * 8 + gid);
                mma_f16(c2a[j], a0, a1, a2, a3, b0, b1);
            }
        }
        __syncthreads();
    }
    // write out0
    {
        int nodeA = node0 + m0 + gid;
        int nodeB = nodeA + 8;
        #pragma unroll
        for (int j = 0; j < 4; j++) {
            int p = n0p2 + j * 8 + 2 * tig;
            if (nodeA < B)
                *(float2*)(out + (size_t)nodeA * 240 + p) = make_float2(c2a[j][0], c2a[j][1]);
            if (nodeB < B)
                *(float2*)(out + (size_t)nodeB * 240 + p) = make_float2(c2a[j][2], c2a[j][3]);
        }
    }

    // =======================================================================
    // Phase 3: out1. 8 q-chunks of 4. GEMM M=64, N=128 (v*4+ql), K=64 (u).
    //   B from global; A'h packed half2 in U: [node][65].
    // =======================================================================
    const float C1 = 0.022097086912079612f;   // 1/sqrt(2048)
    float* Ah = U;                            // 64 x 65 = 4160 words
    const uint32_t* W1 = reinterpret_cast<const uint32_t*>(g_Wsv1p);
    for (int qc = 0; qc < 8; qc++) {
        #pragma unroll
        for (int pass = 0; pass < 2; pass++) {
            float c[4][4];
            #pragma unroll
            for (int j = 0; j < 4; j++)
                #pragma unroll
                for (int i = 0; i < 4; i++) c[j][i] = 0.f;
            #pragma unroll
            for (int ks = 0; ks < 4; ks++) {
                int kb2 = ks * 8;
                uint32_t a0 = sA[(kb2 + tig) * 72 + m0 + gid];
                uint32_t a1 = sA[(kb2 + tig) * 72 + m0 + gid + 8];
                uint32_t a2 = sA[(kb2 + tig + 4) * 72 + m0 + gid];
                uint32_t a3 = sA[(kb2 + tig + 4) * 72 + m0 + gid + 8];
                #pragma unroll
                for (int j = 0; j < 4; j++) {
                    int col = n0w + (pass * 4 + j) * 8 + gid;
                    uint32_t b0 = __ldg(W1 + (size_t)(qc * 32 + kb2 + tig) * 128 + col);
                    uint32_t b1 = __ldg(W1 + (size_t)(qc * 32 + kb2 + tig + 4) * 128 + col);
                    mma_f16(c[j], a0, a1, a2, a3, b0, b1);
                }
            }
            // write A'h packed: [node][col2], pitch 65
            #pragma unroll
            for (int j = 0; j < 4; j++) {
                int col2 = (n0w + (pass * 4 + j) * 8 + 2 * tig) >> 1;
                *reinterpret_cast<half2*>(Ah + (m0 + gid) * 65 + col2) =
                    __floats2half2_rn(c[j][0], c[j][1]);
                *reinterpret_cast<half2*>(Ah + (m0 + gid + 8) * 65 + col2) =
                    __floats2half2_rn(c[j][2], c[j][3]);
            }
        }
        __syncthreads();
        // epilogue: 256 items (node, ql)
        {
            int node = tid & 63, ql = tid >> 6;
            int hsel = ql & 1;
            float o0 = 0.f, o1 = 0.f, o2 = 0.f;
            #pragma unroll 8
            for (int v = 0; v < 32; v++) {
                float a = h2_get(Ah[node * 65 + v * 2 + (ql >> 1)], hsel);
                const float* pvv = svv + (3 * v) * 64 + node;
                o0 += a * pvv[0];
                o1 += a * pvv[64];
                o2 += a * pvv[128];
            }
            int node_g = node0 + node;
            if (node_g < B) {
                float* o = out + (size_t)node_g * 240 + 64 + (qc * 4 + ql) * 3;
                o[0] = C1 * o0; o[1] = C1 * o1; o[2] = C1 * o2;
            }
        }
        __syncthreads();
    }

    // =======================================================================
    // Phase 4: out2. 4 u-chunks x 3 j. GEMM M=64, N=128 (ul*16+r), K=32 (v).
    //   B from global; tvbh packed half2 in U: [node][65]. A from vA.
    // =======================================================================
    float* tvbh = U;
    const uint32_t* W2 = reinterpret_cast<const uint32_t*>(g_Wvv2p);

    float S[4][9];
    #pragma unroll
    for (int t = 0; t < 4; t++)
        #pragma unroll
        for (int i = 0; i < 9; i++) S[t][i] = 0.f;

    for (int uc = 0; uc < 4; uc++) {
        for (int j = 0; j < 3; j++) {
            #pragma unroll
            for (int pass = 0; pass < 2; pass++) {
                float c[4][4];
                #pragma unroll
                for (int jn = 0; jn < 4; jn++)
                    #pragma unroll
                    for (int i = 0; i < 4; i++) c[jn][i] = 0.f;
                #pragma unroll
                for (int ks = 0; ks < 2; ks++) {
                    int kb2 = ks * 8;
                    int arow = j * 16 + kb2;
                    uint32_t a0 = vA[(arow + tig) * 72 + m0 + gid];
                    uint32_t a1 = vA[(arow + tig) * 72 + m0 + gid + 8];
                    uint32_t a2 = vA[(arow + tig + 4) * 72 + m0 + gid];
                    uint32_t a3 = vA[(arow + tig + 4) * 72 + m0 + gid + 8];
                    #pragma unroll
                    for (int jn = 0; jn < 4; jn++) {
                        int col = n0w + (pass * 4 + jn) * 8 + gid;
                        uint32_t b0 = __ldg(W2 + (size_t)(uc * 16 + kb2 + tig) * 128 + col);
                        uint32_t b1 = __ldg(W2 + (size_t)(uc * 16 + kb2 + tig + 4) * 128 + col);
                        mma_f16(c[jn], a0, a1, a2, a3, b0, b1);
                    }
                }
                #pragma unroll
                for (int jn = 0; jn < 4; jn++) {
                    int col2 = (n0w + (pass * 4 + jn) * 8 + 2 * tig) >> 1;
                    *reinterpret_cast<half2*>(tvbh + (m0 + gid) * 65 + col2) =
                        __floats2half2_rn(c[jn][0], c[jn][1]);
                    *reinterpret_cast<half2*>(tvbh + (m0 + gid + 8) * 65 + col2) =
                        __floats2half2_rn(c[jn][2], c[jn][3]);
                }
            }
            __syncthreads();
            // S accumulation: 1024 items (node, r)
            #pragma unroll
            for (int t = 0; t < 4; t++) {
                int it = tid + t * 256;
                int node = it & 63, r = it >> 6;
                int hsel = r & 1;
                #pragma unroll
                for (int ul = 0; ul < 8; ul++) {
                    float tvv = h2_get(tvbh[node * 65 + ul * 8 + (r >> 1)], hsel);
                    const float* pu_ = svv + (3 * (uc * 8 + ul)) * 64 + node;
                    S[t][0 + j] += pu_[0]   * tvv;
                    S[t][3 + j] += pu_[64]  * tvv;
                    S[t][6 + j] += pu_[128] * tvv;
                }
            }
            __syncthreads();
        }
    }
    // finalize out2 via CG contraction
    const float C2R2 = (1.f / 32.f) * 0.7071067811865475f;
    const float C2R6 = (1.f / 32.f) * 0.4082482904638630f;
    #pragma unroll
    for (int t = 0; t < 4; t++) {
        int it = tid + t * 256;
        int node = node0 + (it & 63);
        int r = it >> 6;
        if (node < B) {
            float* o = out + (size_t)node * 240 + 160 + r * 5;
            o[0] = C2R2 * (S[t][1] + S[t][3]);                       // S01+S10
            o[1] = C2R2 * (S[t][5] + S[t][7]);                       // S12+S21
            o[2] = C2R6 * (2.f * S[t][8] - S[t][0] - S[t][4]);       // 2S22-S00-S11
            o[3] = C2R2 * (S[t][2] + S[t][6]);                       // S02+S20
            o[4] = C2R2 * (S[t][0] - S[t][4]);                       // S00-S11
        }
    }
}

// ------------------------------------------------------------------- launcher
extern "C" void kernel_launch(void* const* d_in, const int* in_sizes, int n_in,
                              void* d_out, int out_size)
{
    const float* x     = (const float*)d_in[0];
    const float* gates = (const float*)d_in[1];
    const float* Wss0  = (const float*)d_in[2];
    const float* Wsv1  = (const float*)d_in[3];
    const float* Wvv0  = (const float*)d_in[4];
    const float* Wvv2  = (const float*)d_in[5];
    float* out = (float*)d_out;

    int B = in_sizes[0] / 160;

    prep_desc<<<6, 256>>>();
    prep_wc<<<K2PAD, 64>>>(Wss0, Wvv0);
    prep_sv1<<<128, 256>>>(Wsv1);
    prep_vv2<<<32, 256>>>(Wvv2);

    size_t smem_bytes = (size_t)SMEM_WORDS * sizeof(float);   // 66,176 B
    cudaFuncSetAttribute(k_main, cudaFuncAttributeMaxDynamicSharedMemorySize,
                         (int)smem_bytes);
    int grid = (B + 63) / 64;
    k_main<<<grid, 256, smem_bytes>>>(x, gates, out, B);
}